// round 16
// baseline (speedup 1.0000x reference)
#include <cuda_runtime.h>
#include <cuda_fp16.h>

// Problem constants
#define Bb 32
#define Kk 1024
#define Cc 64
#define Oo 32
#define Ii 32

#define QS   32767.0f          // int16 quant scale
#define QSI  (1.0f / 32767.0f)

#define NKB0 128               // uhat k-blocks (Kk/KPB)
#define NKB1 128               // route k-blocks (Kk/KC3)
#define BCO  (Bb * Cc * Oo)    // 65536
#define BCO2 (BCO / 2)         // 32768 (half2 units per slice)

// ---------------- device scratch (no allocations allowed) ----------------
__device__ unsigned int g_uh[(size_t)Bb * Kk * Cc * Oo / 2]; // int16x2, 134 MB
__device__ unsigned int g_p0h[(size_t)NKB0 * BCO2];          // 16 MB fp16 s0 partials
__device__ unsigned int g_p1h[(size_t)NKB1 * BCO2];          // 16 MB fp16 s1/s2 partials
__device__ float g_v0[BCO];
__device__ float g_v1[BCO];

// ---------------- helpers ------------------------------------------------
__device__ __forceinline__ unsigned int to_tf32(float f) {
    unsigned int r;
    asm("cvt.rna.tf32.f32 %0, %1;" : "=r"(r) : "f"(f));
    return r;
}
__device__ __forceinline__ void mma_tf32(float acc[4],
        unsigned int a0, unsigned int a1, unsigned int a2, unsigned int a3,
        unsigned int b0, unsigned int b1) {
    asm("mma.sync.aligned.m16n8k8.row.col.f32.tf32.tf32.f32 "
        "{%0,%1,%2,%3}, {%4,%5,%6,%7}, {%8,%9}, {%0,%1,%2,%3};"
        : "+f"(acc[0]), "+f"(acc[1]), "+f"(acc[2]), "+f"(acc[3])
        : "r"(a0), "r"(a1), "r"(a2), "r"(a3), "r"(b0), "r"(b1));
}
__device__ __forceinline__ unsigned int packq(float a, float b) {
    int ia = __float2int_rn(a * QS);   // |u_hat| << 1: no clamp needed
    int ib = __float2int_rn(b * QS);
    return (unsigned int)(ia & 0xffff) | ((unsigned int)ib << 16);
}
__device__ __forceinline__ unsigned int packh(float a, float b) {
    __half2 h = __halves2half2(__float2half_rn(a), __float2half_rn(b));
    return *reinterpret_cast<unsigned int*>(&h);
}
__device__ __forceinline__ float2 unpackh(unsigned int u) {
    return __half22float2(*reinterpret_cast<__half2*>(&u));
}
__device__ __forceinline__ void unpack8(uint4 uv, float* uh) {
    uh[0] = (float)((short)(uv.x & 0xffff)); uh[1] = (float)((short)(uv.x >> 16));
    uh[2] = (float)((short)(uv.y & 0xffff)); uh[3] = (float)((short)(uv.y >> 16));
    uh[4] = (float)((short)(uv.z & 0xffff)); uh[5] = (float)((short)(uv.z >> 16));
    uh[6] = (float)((short)(uv.w & 0xffff)); uh[7] = (float)((short)(uv.w >> 16));
}
__device__ __forceinline__ void cpa16(void* dst, const void* src) {
    unsigned int d = (unsigned int)__cvta_generic_to_shared(dst);
    asm volatile("cp.async.cg.shared.global [%0], [%1], 16;"
                 :: "r"(d), "l"(src) : "memory");
}
__device__ __forceinline__ void cp_commit() {
    asm volatile("cp.async.commit_group;" ::: "memory");
}
template <int N> __device__ __forceinline__ void cp_wait() {
    asm volatile("cp.async.wait_group %0;" :: "n"(N) : "memory");
}

// ---------------- Pass 1: u_hat tf32 mma + smem store transpose ----------
// grid=(NKB0, 8 c-eighths), 256 thr, KPB=8 (best measured config).
#define KPB 8
#define SP 36                    // compute-smem row stride (words)
#define WELE (256 * SP)
#define XELE (32 * SP)
#define UBST 132                 // ubuf row stride (uints): 4g+tg banks
#define UELE (32 * UBST)
#define UHAT_SMEM ((2 * WELE + 2 * XELE + UELE) * 4)   // 99,840 B

__global__ void __launch_bounds__(256)
uhat_tf32_kernel(const float* __restrict__ x, const float* __restrict__ W) {
    extern __shared__ float dsm[];
    float* Wb0 = dsm;
    float* Wb1 = dsm + WELE;
    float* Xb0 = dsm + 2 * WELE;
    float* Xb1 = dsm + 2 * WELE + XELE;
    unsigned int* ubuf = reinterpret_cast<unsigned int*>(dsm + 2 * WELE + 2 * XELE);

    const int t = threadIdx.x, lane = t & 31, w = t >> 5;
    const int g = lane >> 2, tg = lane & 3;
    const int q  = blockIdx.y;          // c-eighth
    const int k0 = blockIdx.x * KPB;
    const int c  = q * 8 + w;           // this warp's class

    auto stage = [&](int k, float* Wd, float* Xd) {
        const float4* wg = reinterpret_cast<const float4*>(
            W + ((size_t)k * Cc + q * 8) * (Oo * Ii));
#pragma unroll
        for (int it = 0; it < 8; it++) {
            int p = it * 256 + t, m = p >> 3, j = p & 7;
            cpa16(&Wd[m * SP + 4 * j], wg + p);
        }
        const float4* xg = reinterpret_cast<const float4*>(x);
        int bb = t >> 3, j = t & 7;
        cpa16(&Xd[bb * SP + 4 * j], xg + ((size_t)bb * Kk + k) * 8 + j);
        cp_commit();
    };

    float s0acc[32];
#pragma unroll
    for (int i = 0; i < 32; i++) s0acc[i] = 0.f;

    stage(k0, Wb0, Xb0);

#pragma unroll
    for (int kk = 0; kk < KPB; kk++) {
        const int k = k0 + kk;
        const int cur = kk & 1;
        if (kk + 1 < KPB) {
            stage(k + 1, cur ? Wb0 : Wb1, cur ? Xb0 : Xb1);
            cp_wait<1>();
        } else {
            cp_wait<0>();
        }
        __syncthreads();
        const float* Wc = cur ? Wb1 : Wb0;
        const float* Xc = cur ? Xb1 : Xb0;

        unsigned int wf[4][4][2];
#pragma unroll
        for (int j = 0; j < 4; j++) {
            const int n0 = w * 32 + j * 8;
#pragma unroll
            for (int ks = 0; ks < 4; ks++) {
                wf[j][ks][0] = to_tf32(Wc[(n0 + g) * SP + ks * 8 + tg]);
                wf[j][ks][1] = to_tf32(Wc[(n0 + g) * SP + ks * 8 + tg + 4]);
            }
        }

#pragma unroll
        for (int mt = 0; mt < 2; mt++) {
            const int mb = mt * 16;
            unsigned int af[4][4];
#pragma unroll
            for (int ks = 0; ks < 4; ks++) {
                af[ks][0] = to_tf32(Xc[(mb + g)     * SP + ks * 8 + tg]);
                af[ks][1] = to_tf32(Xc[(mb + g + 8) * SP + ks * 8 + tg]);
                af[ks][2] = to_tf32(Xc[(mb + g)     * SP + ks * 8 + tg + 4]);
                af[ks][3] = to_tf32(Xc[(mb + g + 8) * SP + ks * 8 + tg + 4]);
            }
#pragma unroll
            for (int j = 0; j < 4; j++) {
                float acc[4] = {0.f, 0.f, 0.f, 0.f};
#pragma unroll
                for (int ks = 0; ks < 4; ks++)
                    mma_tf32(acc, af[ks][0], af[ks][1], af[ks][2], af[ks][3],
                             wf[j][ks][0], wf[j][ks][1]);
                s0acc[(mt * 4 + j) * 4 + 0] += acc[0];
                s0acc[(mt * 4 + j) * 4 + 1] += acc[1];
                s0acc[(mt * 4 + j) * 4 + 2] += acc[2];
                s0acc[(mt * 4 + j) * 4 + 3] += acc[3];
                const int ba = mb + g, bb2 = mb + g + 8;
                const int col = w * 16 + 4 * j + tg;
                ubuf[ba  * UBST + col] = packq(acc[0], acc[1]);
                ubuf[bb2 * UBST + col] = packq(acc[2], acc[3]);
            }
        }
        __syncthreads();   // tile complete (also: all reads of cur done)

        // cooperative coalesced flush: warp = one b-row = 512B contiguous
        {
            uint4* gout = reinterpret_cast<uint4*>(
                g_uh + (size_t)k * (Cc * 16) + q * 128);
            const size_t bstride4 = (size_t)Kk * Cc * 4;   // uint4 per b
#pragma unroll
            for (int it = 0; it < 4; it++) {
                int u = it * 256 + t;
                int bi = u >> 5, r4 = u & 31;
                uint4 val = *reinterpret_cast<uint4*>(&ubuf[bi * UBST + r4 * 4]);
                gout[(size_t)bi * bstride4 + r4] = val;
            }
        }
        __syncthreads();   // flush reads done before next k's STS overwrite
    }

    // flush s0 partials: fp16x2 stores into this k-block's slice
    unsigned int* p0 = g_p0h + (size_t)blockIdx.x * BCO2;
#pragma unroll
    for (int mt = 0; mt < 2; mt++)
#pragma unroll
        for (int j = 0; j < 4; j++) {
            int ba = mt * 16 + g, bb2 = ba + 8, oh2 = 4 * j + tg;  // o/2
            p0[(ba  * Cc + c) * 16 + oh2] =
                packh(s0acc[(mt*4+j)*4 + 0], s0acc[(mt*4+j)*4 + 1]);
            p0[(bb2 * Cc + c) * 16 + oh2] =
                packh(s0acc[(mt*4+j)*4 + 2], s0acc[(mt*4+j)*4 + 3]);
        }
}

// ---------------- reduce fp16 partials + squash (block per (b,c) row) ----
// Thread t: sgrp = t>>3 (slice), oq = t&7. Per slice loads uint2 = 4 halves.
__global__ void __launch_bounds__(256)
reduce_squash_kernel(int which, float* __restrict__ ext_out) {
    __shared__ float ps[32][33];   // [sgrp][o], padded

    const unsigned int* part = (which == 0) ? g_p0h : g_p1h;
    float* vout       = (which == 0) ? g_v0 : (which == 1) ? g_v1 : ext_out;
    const float scale = (which == 0) ? (1.0f / Cc) : 1.0f;

    const int t = threadIdx.x;
    const int sgrp = t >> 3, oq = t & 7;
    const uint2* p = reinterpret_cast<const uint2*>(part);
    const size_t base = (size_t)blockIdx.x * 8 + oq;   // uint2 units in slice

    uint2 a0 = p[(size_t)(sgrp)      * (BCO2 / 2) + base];
    uint2 a1 = p[(size_t)(sgrp + 32) * (BCO2 / 2) + base];
    uint2 a2 = p[(size_t)(sgrp + 64) * (BCO2 / 2) + base];
    uint2 a3 = p[(size_t)(sgrp + 96) * (BCO2 / 2) + base];

    float2 f0x = unpackh(a0.x), f1x = unpackh(a1.x),
           f2x = unpackh(a2.x), f3x = unpackh(a3.x);
    float2 f0y = unpackh(a0.y), f1y = unpackh(a1.y),
           f2y = unpackh(a2.y), f3y = unpackh(a3.y);

    ps[sgrp][oq * 4 + 0] = (f0x.x + f1x.x) + (f2x.x + f3x.x);
    ps[sgrp][oq * 4 + 1] = (f0x.y + f1x.y) + (f2x.y + f3x.y);
    ps[sgrp][oq * 4 + 2] = (f0y.x + f1y.x) + (f2y.x + f3y.x);
    ps[sgrp][oq * 4 + 3] = (f0y.y + f1y.y) + (f2y.y + f3y.y);
    __syncthreads();

    if (t < 32) {                      // lane = o
        float v0 = 0.f, v1 = 0.f, v2 = 0.f, v3 = 0.f;
#pragma unroll
        for (int s = 0; s < 32; s += 4) {
            v0 += ps[s][t];     v1 += ps[s + 1][t];
            v2 += ps[s + 2][t]; v3 += ps[s + 3][t];
        }
        float val = ((v0 + v1) + (v2 + v3)) * scale;
        float sq = val * val;
#pragma unroll
        for (int sh = 16; sh > 0; sh >>= 1) sq += __shfl_xor_sync(~0u, sq, sh);
        float f = (sq / (1.0f + sq)) * rsqrtf(sq + 1e-8f);
        vout[(size_t)blockIdx.x * Oo + t] = val * f;
    }
}

// ---------------- routing pass: b1 recomputed, fp16 partial stores -------
// Thread -> (c, oh): c = 8w + (lane>>2), oh = lane&3 (8 o's = 1 uint4).
// Pass 2 recomputes b1 = u.v0 from the SAME registers (bitwise identical
// to pass 1's value) instead of storing/loading it.
#define KC3 8
__global__ void __launch_bounds__(256, 3)
route2_kernel(int iter, float* __restrict__ c_out_ext) {
    __shared__ float tbs[KC3][Cc];        // 2 KB
    __shared__ float csm[KC3][Cc];        // 2 KB

    const int t = threadIdx.x, lane = t & 31, w = t >> 5;
    const int c  = w * 8 + (lane >> 2);
    const int oh = lane & 3;
    const int b  = blockIdx.y;
    const int k0 = blockIdx.x * KC3;

    // ---- prefetches: u_hat tiles + v (+ v0 for pass 2) ----
    uint4 uv[KC3];
#pragma unroll
    for (int kk = 0; kk < KC3; kk++)
        uv[kk] = *reinterpret_cast<const uint4*>(
            &g_uh[(((size_t)b * Kk + k0 + kk) * Cc + c) * 16 + oh * 4]);

    const size_t voff = ((size_t)(b * Cc + c)) * Oo + oh * 8;
    const float* vpN = (iter ? g_v1 : g_v0) + voff;
    float4 va = *reinterpret_cast<const float4*>(vpN);
    float4 vb = *reinterpret_cast<const float4*>(vpN + 4);
    float vvsN[8] = { va.x * QSI, va.y * QSI, va.z * QSI, va.w * QSI,
                      vb.x * QSI, vb.y * QSI, vb.z * QSI, vb.w * QSI };

    float vvs0[8];
    if (iter) {                          // pass 2 also needs v0 (b1 recompute)
        const float* vp0 = g_v0 + voff;
        float4 ca = *reinterpret_cast<const float4*>(vp0);
        float4 cb = *reinterpret_cast<const float4*>(vp0 + 4);
        vvs0[0] = ca.x * QSI; vvs0[1] = ca.y * QSI;
        vvs0[2] = ca.z * QSI; vvs0[3] = ca.w * QSI;
        vvs0[4] = cb.x * QSI; vvs0[5] = cb.y * QSI;
        vvs0[6] = cb.z * QSI; vvs0[7] = cb.w * QSI;
    }

    // ---- Phase A: agreements from registers ----
#pragma unroll
    for (int kk = 0; kk < KC3; kk++) {
        float uh[8];
        unpack8(uv[kk], uh);
        float ap = 0.f;
#pragma unroll
        for (int j = 0; j < 8; j++) ap = fmaf(uh[j], vvsN[j], ap);
        ap += __shfl_xor_sync(~0u, ap, 1);
        ap += __shfl_xor_sync(~0u, ap, 2);       // full sum over o
        if (iter) {                              // recompute b1 (= u.v0)
            float a0 = 0.f;
#pragma unroll
            for (int j = 0; j < 8; j++) a0 = fmaf(uh[j], vvs0[j], a0);
            a0 += __shfl_xor_sync(~0u, a0, 1);
            a0 += __shfl_xor_sync(~0u, a0, 2);
            ap = a0 + ap;                        // b1 + agreement(v1)
        }
        if (oh == 0) tbs[kk][c] = ap;
    }
    __syncthreads();

    // ---- Phase B: softmax, warp w handles k = k0 + w ----
    {
        float tA = tbs[w][lane], tB = tbs[w][lane + 32];
        float eA = __expf(tA), eB = __expf(tB);  // |t| << 1: no max-pass
        float s = eA + eB;
#pragma unroll
        for (int sh = 16; sh > 0; sh >>= 1) s += __shfl_xor_sync(~0u, s, sh);
        float inv = 1.0f / s;                    // exact sum over 64 classes
        float cvA = eA * inv, cvB = eB * inv;
        csm[w][lane]      = cvA;
        csm[w][lane + 32] = cvB;
        if (iter) {
            const size_t bkB = (size_t)b * Kk + k0 + w;
            c_out_ext[bkB * Cc + lane]      = cvA;
            c_out_ext[bkB * Cc + lane + 32] = cvB;
        }
    }
    __syncthreads();

    // ---- Phase C: s accumulation from registers (zero loads) ----
    float sacc[8];
#pragma unroll
    for (int j = 0; j < 8; j++) sacc[j] = 0.f;
#pragma unroll
    for (int kk = 0; kk < KC3; kk++) {
        float uh[8];
        unpack8(uv[kk], uh);
        float cij = csm[kk][c];
#pragma unroll
        for (int j = 0; j < 8; j++) sacc[j] = fmaf(cij, uh[j], sacc[j]);
    }

    // fp16x2 partial store: one STG.128 per thread, coalesced per warp
    unsigned int h0 = packh(sacc[0] * QSI, sacc[1] * QSI);
    unsigned int h1 = packh(sacc[2] * QSI, sacc[3] * QSI);
    unsigned int h2 = packh(sacc[4] * QSI, sacc[5] * QSI);
    unsigned int h3 = packh(sacc[6] * QSI, sacc[7] * QSI);
    uint4* pd = reinterpret_cast<uint4*>(
        g_p1h + ((size_t)blockIdx.x * Bb + b) * BCO2 / NKB1 * NKB1);  // base
    // element offset within slice: (c*32 + oh*8)/2 halves2 -> /4 uint4
    size_t idx = (((size_t)blockIdx.x * Bb + b) * (Cc * 16) + c * 16 + oh * 4) / 4;
    reinterpret_cast<uint4*>(g_p1h)[idx] = make_uint4(h0, h1, h2, h3);
    (void)pd;
}

// ---------------- launch -------------------------------------------------
extern "C" void kernel_launch(void* const* d_in, const int* in_sizes, int n_in,
                              void* d_out, int out_size) {
    const float* x = (const float*)d_in[0];   // [B,K,I]
    const float* W = (const float*)d_in[1];   // [K,C,O,I]
    if (n_in >= 2 && in_sizes[0] > in_sizes[1]) {  // defensive: order by size
        const float* tmp = x; x = W; W = tmp;
    }
    float* out   = (float*)d_out;
    float* v_out = out;                 // [B,C,O]
    float* c_out = out + Bb * Cc * Oo;  // [B,K,C]

    cudaFuncSetAttribute(uhat_tf32_kernel,
                         cudaFuncAttributeMaxDynamicSharedMemorySize, UHAT_SMEM);

    uhat_tf32_kernel<<<dim3(NKB0, 8), 256, UHAT_SMEM>>>(x, W);   // u_hat + p0
    reduce_squash_kernel<<<Bb * Cc, 256>>>(0, nullptr);          // v0
    route2_kernel<<<dim3(NKB1, Bb), 256>>>(0, nullptr);          // p1
    reduce_squash_kernel<<<Bb * Cc, 256>>>(1, nullptr);          // v1
    route2_kernel<<<dim3(NKB1, Bb), 256>>>(1, c_out);            // c_ij, p1
    reduce_squash_kernel<<<Bb * Cc, 256>>>(2, v_out);            // v out
}

// round 17
// speedup vs baseline: 1.0568x; 1.0568x over previous
#include <cuda_runtime.h>
#include <cuda_fp16.h>

// Problem constants
#define Bb 32
#define Kk 1024
#define Cc 64
#define Oo 32
#define Ii 32

#define QS   32767.0f          // int16 quant scale
#define QSI  (1.0f / 32767.0f)

#define NKB0 128               // uhat k-blocks (Kk/KPB)
#define NKB1 128               // route k-blocks (Kk/KC3)
#define BCO  (Bb * Cc * Oo)    // 65536
#define BCO2 (BCO / 2)         // 32768 (half2 units per slice)

// ---------------- device scratch (no allocations allowed) ----------------
__device__ unsigned int g_uh[(size_t)Bb * Kk * Cc * Oo / 2]; // int16x2, 134 MB
__device__ float g_b1[Bb * Kk * Cc];                         // 8 MB
__device__ unsigned int g_p0h[(size_t)NKB0 * BCO2];          // 16 MB fp16 s0 partials
__device__ unsigned int g_p1h[(size_t)NKB1 * BCO2];          // 16 MB fp16 s1/s2 partials
__device__ float g_v0[BCO];
__device__ float g_v1[BCO];
__device__ float g_sink[32];                                 // L2-warm sink

// ---------------- helpers ------------------------------------------------
__device__ __forceinline__ unsigned int to_tf32(float f) {
    unsigned int r;
    asm("cvt.rna.tf32.f32 %0, %1;" : "=r"(r) : "f"(f));
    return r;
}
__device__ __forceinline__ void mma_tf32(float acc[4],
        unsigned int a0, unsigned int a1, unsigned int a2, unsigned int a3,
        unsigned int b0, unsigned int b1) {
    asm("mma.sync.aligned.m16n8k8.row.col.f32.tf32.tf32.f32 "
        "{%0,%1,%2,%3}, {%4,%5,%6,%7}, {%8,%9}, {%0,%1,%2,%3};"
        : "+f"(acc[0]), "+f"(acc[1]), "+f"(acc[2]), "+f"(acc[3])
        : "r"(a0), "r"(a1), "r"(a2), "r"(a3), "r"(b0), "r"(b1));
}
__device__ __forceinline__ unsigned int packq(float a, float b) {
    int ia = __float2int_rn(a * QS);   // |u_hat| << 1: no clamp needed
    int ib = __float2int_rn(b * QS);
    return (unsigned int)(ia & 0xffff) | ((unsigned int)ib << 16);
}
__device__ __forceinline__ unsigned int packh(float a, float b) {
    __half2 h = __halves2half2(__float2half_rn(a), __float2half_rn(b));
    return *reinterpret_cast<unsigned int*>(&h);
}
__device__ __forceinline__ float2 unpackh(unsigned int u) {
    return __half22float2(*reinterpret_cast<__half2*>(&u));
}
__device__ __forceinline__ void unpack8(uint4 uv, float* uh) {
    uh[0] = (float)((short)(uv.x & 0xffff)); uh[1] = (float)((short)(uv.x >> 16));
    uh[2] = (float)((short)(uv.y & 0xffff)); uh[3] = (float)((short)(uv.y >> 16));
    uh[4] = (float)((short)(uv.z & 0xffff)); uh[5] = (float)((short)(uv.z >> 16));
    uh[6] = (float)((short)(uv.w & 0xffff)); uh[7] = (float)((short)(uv.w >> 16));
}
__device__ __forceinline__ void cpa16(void* dst, const void* src) {
    unsigned int d = (unsigned int)__cvta_generic_to_shared(dst);
    asm volatile("cp.async.cg.shared.global [%0], [%1], 16;"
                 :: "r"(d), "l"(src) : "memory");
}
__device__ __forceinline__ void cp_commit() {
    asm volatile("cp.async.commit_group;" ::: "memory");
}
template <int N> __device__ __forceinline__ void cp_wait() {
    asm volatile("cp.async.wait_group %0;" :: "n"(N) : "memory");
}

// ---------------- Pass 1: u_hat tf32 mma + smem store transpose ----------
// grid=(NKB0, 8 c-eighths), 256 thr, KPB=8 (best measured config).
#define KPB 8
#define SP 36                    // compute-smem row stride (words)
#define WELE (256 * SP)
#define XELE (32 * SP)
#define UBST 132                 // ubuf row stride (uints): 4g+tg banks
#define UELE (32 * UBST)
#define UHAT_SMEM ((2 * WELE + 2 * XELE + UELE) * 4)   // 99,840 B

__global__ void __launch_bounds__(256)
uhat_tf32_kernel(const float* __restrict__ x, const float* __restrict__ W) {
    extern __shared__ float dsm[];
    float* Wb0 = dsm;
    float* Wb1 = dsm + WELE;
    float* Xb0 = dsm + 2 * WELE;
    float* Xb1 = dsm + 2 * WELE + XELE;
    unsigned int* ubuf = reinterpret_cast<unsigned int*>(dsm + 2 * WELE + 2 * XELE);

    const int t = threadIdx.x, lane = t & 31, w = t >> 5;
    const int g = lane >> 2, tg = lane & 3;
    const int q  = blockIdx.y;          // c-eighth
    const int k0 = blockIdx.x * KPB;
    const int c  = q * 8 + w;           // this warp's class

    auto stage = [&](int k, float* Wd, float* Xd) {
        const float4* wg = reinterpret_cast<const float4*>(
            W + ((size_t)k * Cc + q * 8) * (Oo * Ii));
#pragma unroll
        for (int it = 0; it < 8; it++) {
            int p = it * 256 + t, m = p >> 3, j = p & 7;
            cpa16(&Wd[m * SP + 4 * j], wg + p);
        }
        const float4* xg = reinterpret_cast<const float4*>(x);
        int bb = t >> 3, j = t & 7;
        cpa16(&Xd[bb * SP + 4 * j], xg + ((size_t)bb * Kk + k) * 8 + j);
        cp_commit();
    };

    float s0acc[32];
#pragma unroll
    for (int i = 0; i < 32; i++) s0acc[i] = 0.f;

    stage(k0, Wb0, Xb0);

#pragma unroll
    for (int kk = 0; kk < KPB; kk++) {
        const int k = k0 + kk;
        const int cur = kk & 1;
        if (kk + 1 < KPB) {
            stage(k + 1, cur ? Wb0 : Wb1, cur ? Xb0 : Xb1);
            cp_wait<1>();
        } else {
            cp_wait<0>();
        }
        __syncthreads();
        const float* Wc = cur ? Wb1 : Wb0;
        const float* Xc = cur ? Xb1 : Xb0;

        unsigned int wf[4][4][2];
#pragma unroll
        for (int j = 0; j < 4; j++) {
            const int n0 = w * 32 + j * 8;
#pragma unroll
            for (int ks = 0; ks < 4; ks++) {
                wf[j][ks][0] = to_tf32(Wc[(n0 + g) * SP + ks * 8 + tg]);
                wf[j][ks][1] = to_tf32(Wc[(n0 + g) * SP + ks * 8 + tg + 4]);
            }
        }

#pragma unroll
        for (int mt = 0; mt < 2; mt++) {
            const int mb = mt * 16;
            unsigned int af[4][4];
#pragma unroll
            for (int ks = 0; ks < 4; ks++) {
                af[ks][0] = to_tf32(Xc[(mb + g)     * SP + ks * 8 + tg]);
                af[ks][1] = to_tf32(Xc[(mb + g + 8) * SP + ks * 8 + tg]);
                af[ks][2] = to_tf32(Xc[(mb + g)     * SP + ks * 8 + tg + 4]);
                af[ks][3] = to_tf32(Xc[(mb + g + 8) * SP + ks * 8 + tg + 4]);
            }
#pragma unroll
            for (int j = 0; j < 4; j++) {
                float acc[4] = {0.f, 0.f, 0.f, 0.f};
#pragma unroll
                for (int ks = 0; ks < 4; ks++)
                    mma_tf32(acc, af[ks][0], af[ks][1], af[ks][2], af[ks][3],
                             wf[j][ks][0], wf[j][ks][1]);
                s0acc[(mt * 4 + j) * 4 + 0] += acc[0];
                s0acc[(mt * 4 + j) * 4 + 1] += acc[1];
                s0acc[(mt * 4 + j) * 4 + 2] += acc[2];
                s0acc[(mt * 4 + j) * 4 + 3] += acc[3];
                const int ba = mb + g, bb2 = mb + g + 8;
                const int col = w * 16 + 4 * j + tg;
                ubuf[ba  * UBST + col] = packq(acc[0], acc[1]);
                ubuf[bb2 * UBST + col] = packq(acc[2], acc[3]);
            }
        }
        __syncthreads();   // tile complete (also: all reads of cur done)

        // cooperative coalesced flush: warp = one b-row = 512B contiguous
        {
            uint4* gout = reinterpret_cast<uint4*>(
                g_uh + (size_t)k * (Cc * 16) + q * 128);
            const size_t bstride4 = (size_t)Kk * Cc * 4;   // uint4 per b
#pragma unroll
            for (int it = 0; it < 4; it++) {
                int u = it * 256 + t;
                int bi = u >> 5, r4 = u & 31;
                uint4 val = *reinterpret_cast<uint4*>(&ubuf[bi * UBST + r4 * 4]);
                gout[(size_t)bi * bstride4 + r4] = val;
            }
        }
        __syncthreads();   // flush reads done before next k's STS overwrite
    }

    // flush s0 partials: fp16x2 stores into this k-block's slice
    unsigned int* p0 = g_p0h + (size_t)blockIdx.x * BCO2;
#pragma unroll
    for (int mt = 0; mt < 2; mt++)
#pragma unroll
        for (int j = 0; j < 4; j++) {
            int ba = mt * 16 + g, bb2 = ba + 8, oh2 = 4 * j + tg;  // o/2
            p0[(ba  * Cc + c) * 16 + oh2] =
                packh(s0acc[(mt*4+j)*4 + 0], s0acc[(mt*4+j)*4 + 1]);
            p0[(bb2 * Cc + c) * 16 + oh2] =
                packh(s0acc[(mt*4+j)*4 + 2], s0acc[(mt*4+j)*4 + 3]);
        }
}

// ---------------- reduce fp16 partials + squash (block per (b,c) row) ----
__global__ void __launch_bounds__(256)
reduce_squash_kernel(int which, float* __restrict__ ext_out) {
    __shared__ float ps[32][33];   // [sgrp][o], padded

    const unsigned int* part = (which == 0) ? g_p0h : g_p1h;
    float* vout       = (which == 0) ? g_v0 : (which == 1) ? g_v1 : ext_out;
    const float scale = (which == 0) ? (1.0f / Cc) : 1.0f;

    const int t = threadIdx.x;
    const int sgrp = t >> 3, oq = t & 7;
    const uint2* p = reinterpret_cast<const uint2*>(part);
    const size_t base = (size_t)blockIdx.x * 8 + oq;   // uint2 units in slice

    uint2 a0 = p[(size_t)(sgrp)      * (BCO2 / 2) + base];
    uint2 a1 = p[(size_t)(sgrp + 32) * (BCO2 / 2) + base];
    uint2 a2 = p[(size_t)(sgrp + 64) * (BCO2 / 2) + base];
    uint2 a3 = p[(size_t)(sgrp + 96) * (BCO2 / 2) + base];

    float2 f0x = unpackh(a0.x), f1x = unpackh(a1.x),
           f2x = unpackh(a2.x), f3x = unpackh(a3.x);
    float2 f0y = unpackh(a0.y), f1y = unpackh(a1.y),
           f2y = unpackh(a2.y), f3y = unpackh(a3.y);

    ps[sgrp][oq * 4 + 0] = (f0x.x + f1x.x) + (f2x.x + f3x.x);
    ps[sgrp][oq * 4 + 1] = (f0x.y + f1x.y) + (f2x.y + f3x.y);
    ps[sgrp][oq * 4 + 2] = (f0y.x + f1y.x) + (f2y.x + f3y.x);
    ps[sgrp][oq * 4 + 3] = (f0y.y + f1y.y) + (f2y.y + f3y.y);
    __syncthreads();

    if (t < 32) {                      // lane = o
        float v0 = 0.f, v1 = 0.f, v2 = 0.f, v3 = 0.f;
#pragma unroll
        for (int s = 0; s < 32; s += 4) {
            v0 += ps[s][t];     v1 += ps[s + 1][t];
            v2 += ps[s + 2][t]; v3 += ps[s + 3][t];
        }
        float val = ((v0 + v1) + (v2 + v3)) * scale;
        float sq = val * val;
#pragma unroll
        for (int sh = 16; sh > 0; sh >>= 1) sq += __shfl_xor_sync(~0u, sq, sh);
        float f = (sq / (1.0f + sq)) * rsqrtf(sq + 1e-8f);
        vout[(size_t)blockIdx.x * Oo + t] = val * f;
    }
}

// ---------------- L2 warm for b1 before route pass 2 ---------------------
__global__ void l2warm_b1_kernel() {
    size_t i = ((size_t)blockIdx.x * 256 + threadIdx.x) * 4;
    float4 v = *reinterpret_cast<const float4*>(&g_b1[i]);
    float s = (v.x + v.y) + (v.z + v.w);
    if (__float_as_uint(s) == 0x7f800000u) g_sink[threadIdx.x & 31] = s;
}

// ---------------- routing pass: b1 store/load (R15), fp16 p1 stores ------
// Thread -> (c, oh): c = 8w + (lane>>2), oh = lane&3 (8 o's = 1 uint4).
#define KC3 8
__global__ void __launch_bounds__(256, 3)
route2_kernel(int iter, float* __restrict__ c_out_ext) {
    __shared__ float tbs[KC3][Cc];        // 2 KB
    __shared__ float csm[KC3][Cc];        // 2 KB

    const int t = threadIdx.x, lane = t & 31, w = t >> 5;
    const int c  = w * 8 + (lane >> 2);
    const int oh = lane & 3;
    const int b  = blockIdx.y;
    const int k0 = blockIdx.x * KC3;

    const float* v = iter ? g_v1 : g_v0;

    // ---- prefetches: u_hat tiles + v + (pass 2) b1, all before any use ----
    uint4 uv[KC3];
#pragma unroll
    for (int kk = 0; kk < KC3; kk++)
        uv[kk] = *reinterpret_cast<const uint4*>(
            &g_uh[(((size_t)b * Kk + k0 + kk) * Cc + c) * 16 + oh * 4]);

    const float* vp = v + ((size_t)(b * Cc + c)) * Oo + oh * 8;
    float4 va = *reinterpret_cast<const float4*>(vp);
    float4 vb = *reinterpret_cast<const float4*>(vp + 4);

    float bA = 0.f, bB = 0.f;      // phase-B b1 operands (warp w owns k=k0+w)
    const size_t bkB = (size_t)b * Kk + k0 + w;
    if (iter) {
        bA = g_b1[bkB * Cc + lane];
        bB = g_b1[bkB * Cc + lane + 32];
    }

    float vvs[8] = { va.x * QSI, va.y * QSI, va.z * QSI, va.w * QSI,
                     vb.x * QSI, vb.y * QSI, vb.z * QSI, vb.w * QSI };

    // ---- Phase A: agreements from registers ----
#pragma unroll
    for (int kk = 0; kk < KC3; kk++) {
        float uh[8];
        unpack8(uv[kk], uh);
        float ap = 0.f;
#pragma unroll
        for (int j = 0; j < 8; j++) ap = fmaf(uh[j], vvs[j], ap);
        ap += __shfl_xor_sync(~0u, ap, 1);
        ap += __shfl_xor_sync(~0u, ap, 2);       // full sum over o
        if (oh == 0) tbs[kk][c] = ap;
    }
    __syncthreads();

    // ---- Phase B: softmax, warp w handles k = k0 + w ----
    {
        float tA = tbs[w][lane] + bA;
        float tB = tbs[w][lane + 32] + bB;
        float eA = __expf(tA), eB = __expf(tB);  // |t| << 1: no max-pass
        float s = eA + eB;
#pragma unroll
        for (int sh = 16; sh > 0; sh >>= 1) s += __shfl_xor_sync(~0u, s, sh);
        float inv = 1.0f / s;                    // exact sum over 64 classes
        float cvA = eA * inv, cvB = eB * inv;
        csm[w][lane]      = cvA;
        csm[w][lane + 32] = cvB;
        if (iter) {
            c_out_ext[bkB * Cc + lane]      = cvA;
            c_out_ext[bkB * Cc + lane + 32] = cvB;
        } else {
            g_b1[bkB * Cc + lane]      = tA;
            g_b1[bkB * Cc + lane + 32] = tB;
        }
    }
    __syncthreads();

    // ---- Phase C: s accumulation from registers (zero loads) ----
    float sacc[8];
#pragma unroll
    for (int j = 0; j < 8; j++) sacc[j] = 0.f;
#pragma unroll
    for (int kk = 0; kk < KC3; kk++) {
        float uh[8];
        unpack8(uv[kk], uh);
        float cij = csm[kk][c];
#pragma unroll
        for (int j = 0; j < 8; j++) sacc[j] = fmaf(cij, uh[j], sacc[j]);
    }

    // fp16x2 partial store: one STG.128 per thread, coalesced per warp
    unsigned int h0 = packh(sacc[0] * QSI, sacc[1] * QSI);
    unsigned int h1 = packh(sacc[2] * QSI, sacc[3] * QSI);
    unsigned int h2 = packh(sacc[4] * QSI, sacc[5] * QSI);
    unsigned int h3 = packh(sacc[6] * QSI, sacc[7] * QSI);
    size_t idx = (((size_t)blockIdx.x * Bb + b) * (Cc * 16) + c * 16 + oh * 4) / 4;
    reinterpret_cast<uint4*>(g_p1h)[idx] = make_uint4(h0, h1, h2, h3);
}

// ---------------- launch -------------------------------------------------
extern "C" void kernel_launch(void* const* d_in, const int* in_sizes, int n_in,
                              void* d_out, int out_size) {
    const float* x = (const float*)d_in[0];   // [B,K,I]
    const float* W = (const float*)d_in[1];   // [K,C,O,I]
    if (n_in >= 2 && in_sizes[0] > in_sizes[1]) {  // defensive: order by size
        const float* tmp = x; x = W; W = tmp;
    }
    float* out   = (float*)d_out;
    float* v_out = out;                 // [B,C,O]
    float* c_out = out + Bb * Cc * Oo;  // [B,K,C]

    cudaFuncSetAttribute(uhat_tf32_kernel,
                         cudaFuncAttributeMaxDynamicSharedMemorySize, UHAT_SMEM);

    uhat_tf32_kernel<<<dim3(NKB0, 8), 256, UHAT_SMEM>>>(x, W);   // u_hat + p0
    reduce_squash_kernel<<<Bb * Cc, 256>>>(0, nullptr);          // v0
    route2_kernel<<<dim3(NKB1, Bb), 256>>>(0, nullptr);          // b1, p1
    reduce_squash_kernel<<<Bb * Cc, 256>>>(1, nullptr);          // v1
    l2warm_b1_kernel<<<(Bb * Kk * Cc / 4) / 256, 256>>>();       // b1 -> L2
    route2_kernel<<<dim3(NKB1, Bb), 256>>>(1, c_out);            // c_ij, p1
    reduce_squash_kernel<<<Bb * Cc, 256>>>(2, v_out);            // v out
}